// round 4
// baseline (speedup 1.0000x reference)
#include <cuda_runtime.h>
#include <math.h>

#define BATCH 512
#define HO 31
#define WO 31
#define HW 64
#define PLANE (HO * WO)
#define TILES_PER_B 4                 // 4 tiles of 8 rows cover HO=31
#define NTILES (BATCH * TILES_PER_B)  // 2048
#define GRID 1024                     // each block handles exactly 2 tiles

// Per-patch closed-form invariants of the quantum circuit:
//   S2 = sum p_i^2 ; D2 = signed sum of p_i^2 (CNOT-ring MSB-half membership)
//   dP = sum over pairs (i, i^12): rows 0<->3 and 1<->2, same column
// Outputs: per-kernel 3x2 linear map of (D2/S2, dP/S2); coefficients depend
// only on U3 of qubit 0 (wires-1..3 unitary cancels: real input, wire-0 obs).

__global__ __launch_bounds__(256) void qconv_kernel(const float* __restrict__ x,
                                                    const float* __restrict__ w,
                                                    float* __restrict__ out) {
    __shared__ float cf[24];
    const int tid = threadIdx.y * 32 + threadIdx.x;
    if (tid < 4) {
        const int k = tid;
        float th = w[k * 12 + 0], ph = w[k * 12 + 1], om = w[k * 12 + 2];
        float st, ct, spo, cpo, smp, cmp, sp, cp, som, com_;
        sincosf(th, &st, &ct);
        sincosf(ph, &sp, &cp);
        sincosf(ph + om, &spo, &cpo);
        sincosf(om - ph, &smp, &cmp);
        sincosf(om, &som, &com_);
        float c2 = 0.5f * (1.0f + ct);  // cos^2(theta/2)
        float s2 = 0.5f * (1.0f - ct);  // sin^2(theta/2)
        cf[k * 6 + 0] = st * cp;
        cf[k * 6 + 1] = 2.0f * (c2 * cpo - s2 * cmp);
        cf[k * 6 + 2] = st * sp;
        cf[k * 6 + 3] = 2.0f * (c2 * spo + s2 * smp);
        cf[k * 6 + 4] = ct;
        cf[k * 6 + 5] = -2.0f * st * com_;
    }
    __syncthreads();

    const int lane = threadIdx.x;  // = wo for lanes 0..30; lane 31 helps load

    for (int tile = blockIdx.x; tile < NTILES; tile += GRID) {
        const int b = tile >> 2;
        const int ho = (tile & 3) * 8 + threadIdx.y;
        if (ho >= HO) continue;  // uniform per warp (depends on threadIdx.y only)

        // Row floats [2*lane, 2*lane+1]; lane 31 fetches the row tail (62,63).
        const float* base = x + (size_t)b * (HW * HW) + (ho * 2) * HW + lane * 2;
        float2 u[4];
#pragma unroll
        for (int r = 0; r < 4; ++r)
            u[r] = *reinterpret_cast<const float2*>(base + r * HW);

        // v (patch cols 2,3) = next lane's u — warp shuffle instead of reload
        float vx[4], vy[4];
#pragma unroll
        for (int r = 0; r < 4; ++r) {
            vx[r] = __shfl_down_sync(0xffffffffu, u[r].x, 1);
            vy[r] = __shfl_down_sync(0xffffffffu, u[r].y, 1);
        }

        if (lane < WO) {
            float S2 = 0.f, D2 = 0.f;
#pragma unroll
            for (int r = 0; r < 4; ++r) {
                float a = u[r].x * u[r].x, bq = u[r].y * u[r].y;
                float c = vx[r] * vx[r], d = vy[r] * vy[r];
                S2 += a + bq + c + d;
                float ds = a - bq - c + d;
                D2 += (r & 1) ? -ds : ds;
            }
            float dP = u[0].x * u[3].x + u[0].y * u[3].y + vx[0] * vx[3] + vy[0] * vy[3]
                     + u[1].x * u[2].x + u[1].y * u[2].y + vx[1] * vx[2] + vy[1] * vy[2];

            float inv = 1.0f / S2;  // reference eps cancels exactly
            float Dl = D2 * inv;
            float dd = dP * inv;

            size_t obase = (size_t)b * 12 * PLANE + ho * WO + lane;
#pragma unroll
            for (int k = 0; k < 4; ++k) {
                out[obase + (size_t)(3 * k + 0) * PLANE] = cf[k * 6 + 0] * Dl + cf[k * 6 + 1] * dd;
                out[obase + (size_t)(3 * k + 1) * PLANE] = cf[k * 6 + 2] * Dl + cf[k * 6 + 3] * dd;
                out[obase + (size_t)(3 * k + 2) * PLANE] = cf[k * 6 + 4] * Dl + cf[k * 6 + 5] * dd;
            }
        }
    }
}

extern "C" void kernel_launch(void* const* d_in, const int* in_sizes, int n_in,
                              void* d_out, int out_size) {
    const float* x = (const float*)d_in[0];
    const float* w = (const float*)d_in[1];
    if (n_in >= 2 && in_sizes[0] == 48) {  // robustness: weights listed first
        x = (const float*)d_in[1];
        w = (const float*)d_in[0];
    }
    float* out = (float*)d_out;

    dim3 blk(32, 8, 1);
    dim3 grd(GRID, 1, 1);
    qconv_kernel<<<grd, blk>>>(x, w, out);
}